// round 4
// baseline (speedup 1.0000x reference)
#include <cuda_runtime.h>

#define D 64
#define NB 1024
#define XS 68   // padded smem row stride (floats)

// Scratch (allocation-free rule: __device__ globals)
__device__ __align__(16) float g_Wt[8 * D * D];    // Wt[m][e*64+d] = W[m][d*64+e]
__device__ __align__(16) float g_UA[NB * 8 * D];   // u1 + S
__device__ __align__(16) float g_UB[NB * 8 * D];   // S * u1
__device__ __align__(16) float g_dise[NB * D];     // emb_dise

typedef unsigned long long ull;

__device__ __forceinline__ float leaky(float x) { return fmaxf(x, 0.2f * x); }
__device__ __forceinline__ float avgw(int cnt)  { return cnt > 0 ? 1.0f / ((float)cnt + 1e-8f) : 0.0f; }

__device__ __forceinline__ ull pack2(float x, float y) {
    ull r; asm("mov.b64 %0, {%1, %2};" : "=l"(r) : "f"(x), "f"(y)); return r;
}
__device__ __forceinline__ float2 unpack2(ull v) {
    float2 f; asm("mov.b64 {%0, %1}, %2;" : "=f"(f.x), "=f"(f.y) : "l"(v)); return f;
}
__device__ __forceinline__ void fma2(ull& acc, ull a, ull b) {
    asm("fma.rn.f32x2 %0, %1, %2, %3;" : "=l"(acc) : "l"(a), "l"(b), "l"(acc));
}

// ---------------------------------------------------------------------------
// K0: coalesced smem-tiled transpose, one block per matrix
// ---------------------------------------------------------------------------
__global__ void __launch_bounds__(1024)
k_transpose(const float* __restrict__ w0, const float* __restrict__ w1,
            const float* __restrict__ w2, const float* __restrict__ w3,
            const float* __restrict__ w4, const float* __restrict__ w5,
            const float* __restrict__ w6, const float* __restrict__ w7) {
    const float* Ws[8] = {w0, w1, w2, w3, w4, w5, w6, w7};
    __shared__ float sm[D * 65];
    int m = blockIdx.x;
    const float* W = Ws[m];
    int t = threadIdx.x;
#pragma unroll
    for (int p = 0; p < 4; ++p) {
        int idx = p * 1024 + t;            // linear over W: d = idx>>6, e = idx&63
        sm[(idx & 63) * 65 + (idx >> 6)] = W[idx];   // sm[e][d], conflict-free
    }
    __syncthreads();
#pragma unroll
    for (int p = 0; p < 4; ++p) {
        int idx = p * 1024 + t;            // linear over Wt: e = idx>>6, d = idx&63
        g_Wt[m * D * D + idx] = sm[(idx >> 6) * 65 + (idx & 63)];
    }
}

// ---------------------------------------------------------------------------
// K1: blocks [0, 8192): usu inner per (b,g). blocks [8192, 9216): dsd per b.
// 128 threads = 8 groups x 16 lanes (4 dims each).
// ---------------------------------------------------------------------------
__global__ void __launch_bounds__(128)
k_inner(const float* __restrict__ E_s, const float* __restrict__ E_d,
        const int* __restrict__ label,
        const int* __restrict__ dsd_1, const int* __restrict__ dsd_2,
        const int* __restrict__ usu_1, const int* __restrict__ usu_2,
        const int* __restrict__ usu_3) {
    int t = threadIdx.x;
    int g16 = t >> 4, lane = t & 15, d4 = lane * 4;

    __shared__ float shX[8][XS];
    __shared__ float shY[8][XS];
    __shared__ float shP[8][8][D];
    __shared__ float shL[4][XS];

    if (blockIdx.x < NB * 8) {
        // ===================== usu inner: one (b,g) per block ================
        int bg = blockIdx.x;

        // prefetch emit operands (t<16 only)
        float4 u = make_float4(0.f, 0.f, 0.f, 0.f);
        int c2 = 0;
        if (t < 16) {
            int iu = __ldg(usu_1 + bg);
            u = *(const float4*)(E_s + iu * D + t * 4);
            int4 m0 = *(const int4*)(usu_2 + bg * 8);
            int4 m1 = *(const int4*)(usu_2 + bg * 8 + 4);
            c2 = (m0.x != 0) + (m0.y != 0) + (m0.z != 0) + (m0.w != 0)
               + (m1.x != 0) + (m1.y != 0) + (m1.z != 0) + (m1.w != 0);
        }

        // row-j indices directly from global (broadcast within 16-lane group)
        const int4* ip = (const int4*)(usu_3 + (bg * 8 + g16) * 16);
        int4 i0 = ip[0], i1 = ip[1], i2 = ip[2], i3 = ip[3];
        int cnt = (i0.x != 0) + (i0.y != 0) + (i0.z != 0) + (i0.w != 0)
                + (i1.x != 0) + (i1.y != 0) + (i1.z != 0) + (i1.w != 0)
                + (i2.x != 0) + (i2.y != 0) + (i2.z != 0) + (i2.w != 0)
                + (i3.x != 0) + (i3.y != 0) + (i3.z != 0) + (i3.w != 0);

        float sx = 0.f, sy = 0.f, sz = 0.f, sw = 0.f;
#define ACC(ix) { float4 v = *(const float4*)(E_s + (ix) * D + d4); \
                  sx += v.x; sy += v.y; sz += v.z; sw += v.w; }
        ACC(i0.x) ACC(i0.y) ACC(i0.z) ACC(i0.w)
        ACC(i1.x) ACC(i1.y) ACC(i1.z) ACC(i1.w)
        ACC(i2.x) ACC(i2.y) ACC(i2.z) ACC(i2.w)
        ACC(i3.x) ACC(i3.y) ACC(i3.z) ACC(i3.w)
#undef ACC
        float w = avgw(cnt);
        *(float4*)&shX[g16][d4] = make_float4(sx * w, sy * w, sz * w, sw * w);
        __syncthreads();

        // matvec W3 (chunk c = g16)
        {
            const float* W3t = g_Wt + 4 * D * D;
            ull aL[8], aH[8];
#pragma unroll
            for (int j = 0; j < 8; ++j) { aL[j] = 0ull; aH[j] = 0ull; }
#pragma unroll
            for (int eo = 0; eo < 8; ++eo) {
                int e = g16 * 8 + eo;
                ulonglong2 wv = *(const ulonglong2*)(W3t + e * D + d4);
#pragma unroll
                for (int j = 0; j < 8; ++j) {
                    ull xx = pack2(shX[j][e], shX[j][e]);
                    fma2(aL[j], xx, wv.x);
                    fma2(aH[j], xx, wv.y);
                }
            }
#pragma unroll
            for (int j = 0; j < 8; ++j) {
                float2 lo = unpack2(aL[j]), hi = unpack2(aH[j]);
                *(float4*)&shP[g16][j][d4] = make_float4(lo.x, lo.y, hi.x, hi.y);
            }
        }
        __syncthreads();

        // reduce chunks + leaky + pairwise j via shfl
        {
            float rx = 0.f, ry = 0.f, rz = 0.f, rw = 0.f;
#pragma unroll
            for (int c = 0; c < 8; ++c) {
                float4 p = *(float4*)&shP[c][g16][d4];
                rx += p.x; ry += p.y; rz += p.z; rw += p.w;
            }
            rx = leaky(rx); ry = leaky(ry); rz = leaky(rz); rw = leaky(rw);
            rx += __shfl_down_sync(0xffffffffu, rx, 16);
            ry += __shfl_down_sync(0xffffffffu, ry, 16);
            rz += __shfl_down_sync(0xffffffffu, rz, 16);
            rw += __shfl_down_sync(0xffffffffu, rw, 16);
            if ((t & 16) == 0)
                *(float4*)&shL[t >> 5][d4] = make_float4(rx, ry, rz, rw);
        }
        __syncthreads();

        // emit UA/UB
        if (t < 16) {
            int dd = t * 4;
            float Sx = 0.f, Sy = 0.f, Sz = 0.f, Sw = 0.f;
#pragma unroll
            for (int wi = 0; wi < 4; ++wi) {
                float4 l = *(float4*)&shL[wi][dd];
                Sx += l.x; Sy += l.y; Sz += l.z; Sw += l.w;
            }
            float w2 = avgw(c2);
            Sx *= w2; Sy *= w2; Sz *= w2; Sw *= w2;
            *(float4*)&g_UA[bg * D + dd] = make_float4(u.x + Sx, u.y + Sy, u.z + Sz, u.w + Sw);
            *(float4*)&g_UB[bg * D + dd] = make_float4(Sx * u.x, Sy * u.y, Sz * u.z, Sw * u.w);
        }
    } else {
        // ===================== dsd full path: one b per block ================
        int b = blockIdx.x - NB * 8;
        int r = g16;

        float4 td4 = make_float4(0.f, 0.f, 0.f, 0.f);
        int c1 = 0;
        if (t < 16) {
            int lb = __ldg(label + b);
            td4 = *(const float4*)(E_d + lb * D + t * 4);
            int4 m0 = *(const int4*)(dsd_1 + b * 8);
            int4 m1 = *(const int4*)(dsd_1 + b * 8 + 4);
            c1 = (m0.x != 0) + (m0.y != 0) + (m0.z != 0) + (m0.w != 0)
               + (m1.x != 0) + (m1.y != 0) + (m1.z != 0) + (m1.w != 0);
        }

        int ies = __ldg(dsd_1 + b * 8 + r);
        const int4* ip = (const int4*)(dsd_2 + (b * 8 + r) * 8);
        int4 i0 = ip[0], i1 = ip[1];
        int cnt = (i0.x != 0) + (i0.y != 0) + (i0.z != 0) + (i0.w != 0)
                + (i1.x != 0) + (i1.y != 0) + (i1.z != 0) + (i1.w != 0);

        float4 es = *(const float4*)(E_s + ies * D + d4);
        float sx = 0.f, sy = 0.f, sz = 0.f, sw = 0.f;
#define ACC(ix) { float4 v = *(const float4*)(E_d + (ix) * D + d4); \
                  sx += v.x; sy += v.y; sz += v.z; sw += v.w; }
        ACC(i0.x) ACC(i0.y) ACC(i0.z) ACC(i0.w)
        ACC(i1.x) ACC(i1.y) ACC(i1.z) ACC(i1.w)
#undef ACC
        float w = avgw(cnt);
        float ax = sx * w, ay = sy * w, az = sz * w, aw = sw * w;
        *(float4*)&shX[r][d4] = make_float4(es.x + ax, es.y + ay, es.z + az, es.w + aw);
        *(float4*)&shY[r][d4] = make_float4(ax * es.x, ay * es.y, az * es.z, aw * es.w);
        __syncthreads();

        // hop1 dual matvec W21/W22 (chunk c = g16)
        {
            const float* W21t = g_Wt + 0 * D * D;
            const float* W22t = g_Wt + 1 * D * D;
            ull aL[8], aH[8];
#pragma unroll
            for (int j = 0; j < 8; ++j) { aL[j] = 0ull; aH[j] = 0ull; }
#pragma unroll
            for (int eo = 0; eo < 8; ++eo) {
                int e = g16 * 8 + eo;
                ulonglong2 wa = *(const ulonglong2*)(W21t + e * D + d4);
                ulonglong2 wb = *(const ulonglong2*)(W22t + e * D + d4);
#pragma unroll
                for (int j = 0; j < 8; ++j) {
                    ull a2 = pack2(shX[j][e], shX[j][e]);
                    ull b2 = pack2(shY[j][e], shY[j][e]);
                    fma2(aL[j], a2, wa.x); fma2(aL[j], b2, wb.x);
                    fma2(aH[j], a2, wa.y); fma2(aH[j], b2, wb.y);
                }
            }
#pragma unroll
            for (int j = 0; j < 8; ++j) {
                float2 lo = unpack2(aL[j]), hi = unpack2(aH[j]);
                *(float4*)&shP[g16][j][d4] = make_float4(lo.x, lo.y, hi.x, hi.y);
            }
        }
        __syncthreads();

        // reduce + leaky + pairwise shfl
        {
            float rx = 0.f, ry = 0.f, rz = 0.f, rw = 0.f;
#pragma unroll
            for (int c = 0; c < 8; ++c) {
                float4 p = *(float4*)&shP[c][g16][d4];
                rx += p.x; ry += p.y; rz += p.z; rw += p.w;
            }
            rx = leaky(rx); ry = leaky(ry); rz = leaky(rz); rw = leaky(rw);
            rx += __shfl_down_sync(0xffffffffu, rx, 16);
            ry += __shfl_down_sync(0xffffffffu, ry, 16);
            rz += __shfl_down_sync(0xffffffffu, rz, 16);
            rw += __shfl_down_sync(0xffffffffu, rw, 16);
            if ((t & 16) == 0)
                *(float4*)&shL[t >> 5][d4] = make_float4(rx, ry, rz, rw);
        }
        __syncthreads();

        // hop2 inputs
        if (t < 16) {
            int dd = t * 4;
            float Ax = 0.f, Ay = 0.f, Az = 0.f, Aw = 0.f;
#pragma unroll
            for (int wi = 0; wi < 4; ++wi) {
                float4 l = *(float4*)&shL[wi][dd];
                Ax += l.x; Ay += l.y; Az += l.z; Aw += l.w;
            }
            float w1 = avgw(c1);
            Ax *= w1; Ay *= w1; Az *= w1; Aw *= w1;
            *(float4*)&shX[0][dd] = make_float4(Ax + td4.x, Ay + td4.y, Az + td4.z, Aw + td4.w);
            *(float4*)&shY[0][dd] = make_float4(Ax * td4.x, Ay * td4.y, Az * td4.z, Aw * td4.w);
        }
        __syncthreads();

        // hop2 dual matvec W11/W12 (1 row)
        {
            const float* W11t = g_Wt + 2 * D * D;
            const float* W12t = g_Wt + 3 * D * D;
            ull aL = 0ull, aH = 0ull;
#pragma unroll
            for (int eo = 0; eo < 8; ++eo) {
                int e = g16 * 8 + eo;
                ulonglong2 wa = *(const ulonglong2*)(W11t + e * D + d4);
                ulonglong2 wb = *(const ulonglong2*)(W12t + e * D + d4);
                ull a2 = pack2(shX[0][e], shX[0][e]);
                ull b2 = pack2(shY[0][e], shY[0][e]);
                fma2(aL, a2, wa.x); fma2(aL, b2, wb.x);
                fma2(aH, a2, wa.y); fma2(aH, b2, wb.y);
            }
            float2 lo = unpack2(aL), hi = unpack2(aH);
            *(float4*)&shP[g16][0][d4] = make_float4(lo.x, lo.y, hi.x, hi.y);
        }
        __syncthreads();

        if (t < 16) {
            int dd = t * 4;
            float rx = 0.f, ry = 0.f, rz = 0.f, rw = 0.f;
#pragma unroll
            for (int c = 0; c < 8; ++c) {
                float4 p = *(float4*)&shP[c][0][dd];
                rx += p.x; ry += p.y; rz += p.z; rw += p.w;
            }
            *(float4*)&g_dise[b * D + dd] =
                make_float4(leaky(rx), leaky(ry), leaky(rz), leaky(rw));
        }
    }
}

// ---------------------------------------------------------------------------
// K2: final per-batch kernel: es1 matvec + i-avg + W1u matvec + dot with dise
// ---------------------------------------------------------------------------
__global__ void __launch_bounds__(128)
k_final(const int* __restrict__ usu_1, float* __restrict__ out) {
    int b = blockIdx.x;
    int t = threadIdx.x;
    int g16 = t >> 4, lane = t & 15, d4 = lane * 4;

    __shared__ float shA[8][XS];
    __shared__ float shB[8][XS];
    __shared__ float shP[8][8][D];
    __shared__ float shL[4][XS];

    // prefetch (t<16): emb_dise and usu_1 mask count
    float4 dz = make_float4(0.f, 0.f, 0.f, 0.f);
    int c1 = 0;
    if (t < 16) {
        dz = *(const float4*)&g_dise[b * D + t * 4];
        int4 m0 = *(const int4*)(usu_1 + b * 8);
        int4 m1 = *(const int4*)(usu_1 + b * 8 + 4);
        c1 = (m0.x != 0) + (m0.y != 0) + (m0.z != 0) + (m0.w != 0)
           + (m1.x != 0) + (m1.y != 0) + (m1.z != 0) + (m1.w != 0);
    }

    // load UA/UB rows (row = g16)
    *(float4*)&shA[g16][d4] = *(const float4*)&g_UA[(b * 8 + g16) * D + d4];
    *(float4*)&shB[g16][d4] = *(const float4*)&g_UB[(b * 8 + g16) * D + d4];
    __syncthreads();

    // es1 dual matvec W21u/W22u (chunk c = g16)
    {
        const float* W21t = g_Wt + 5 * D * D;
        const float* W22t = g_Wt + 6 * D * D;
        ull aL[8], aH[8];
#pragma unroll
        for (int j = 0; j < 8; ++j) { aL[j] = 0ull; aH[j] = 0ull; }
#pragma unroll
        for (int eo = 0; eo < 8; ++eo) {
            int e = g16 * 8 + eo;
            ulonglong2 wa = *(const ulonglong2*)(W21t + e * D + d4);
            ulonglong2 wb = *(const ulonglong2*)(W22t + e * D + d4);
#pragma unroll
            for (int j = 0; j < 8; ++j) {
                ull a2 = pack2(shA[j][e], shA[j][e]);
                ull b2 = pack2(shB[j][e], shB[j][e]);
                fma2(aL[j], a2, wa.x); fma2(aL[j], b2, wb.x);
                fma2(aH[j], a2, wa.y); fma2(aH[j], b2, wb.y);
            }
        }
#pragma unroll
        for (int j = 0; j < 8; ++j) {
            float2 lo = unpack2(aL[j]), hi = unpack2(aH[j]);
            *(float4*)&shP[g16][j][d4] = make_float4(lo.x, lo.y, hi.x, hi.y);
        }
    }
    __syncthreads();

    // reduce + leaky + pairwise shfl
    {
        float rx = 0.f, ry = 0.f, rz = 0.f, rw = 0.f;
#pragma unroll
        for (int c = 0; c < 8; ++c) {
            float4 p = *(float4*)&shP[c][g16][d4];
            rx += p.x; ry += p.y; rz += p.z; rw += p.w;
        }
        rx = leaky(rx); ry = leaky(ry); rz = leaky(rz); rw = leaky(rw);
        rx += __shfl_down_sync(0xffffffffu, rx, 16);
        ry += __shfl_down_sync(0xffffffffu, ry, 16);
        rz += __shfl_down_sync(0xffffffffu, rz, 16);
        rw += __shfl_down_sync(0xffffffffu, rw, 16);
        if ((t & 16) == 0)
            *(float4*)&shL[t >> 5][d4] = make_float4(rx, ry, rz, rw);
    }
    __syncthreads();

    // i-avg
    if (t < 16) {
        int dd = t * 4;
        float Tx = 0.f, Ty = 0.f, Tz = 0.f, Tw = 0.f;
#pragma unroll
        for (int wi = 0; wi < 4; ++wi) {
            float4 l = *(float4*)&shL[wi][dd];
            Tx += l.x; Ty += l.y; Tz += l.z; Tw += l.w;
        }
        float w1 = avgw(c1);
        *(float4*)&shA[0][dd] = make_float4(Tx * w1, Ty * w1, Tz * w1, Tw * w1);
    }
    __syncthreads();

    // emb_user matvec W1u (1 row)
    {
        const float* W1t = g_Wt + 7 * D * D;
        ull aL = 0ull, aH = 0ull;
#pragma unroll
        for (int eo = 0; eo < 8; ++eo) {
            int e = g16 * 8 + eo;
            ulonglong2 wv = *(const ulonglong2*)(W1t + e * D + d4);
            ull xx = pack2(shA[0][e], shA[0][e]);
            fma2(aL, xx, wv.x);
            fma2(aH, xx, wv.y);
        }
        float2 lo = unpack2(aL), hi = unpack2(aH);
        *(float4*)&shP[g16][0][d4] = make_float4(lo.x, lo.y, hi.x, hi.y);
    }
    __syncthreads();

    // final reduce + dot with emb_dise
    if (t < 16) {
        int dd = t * 4;
        float rx = 0.f, ry = 0.f, rz = 0.f, rw = 0.f;
#pragma unroll
        for (int c = 0; c < 8; ++c) {
            float4 p = *(float4*)&shP[c][0][dd];
            rx += p.x; ry += p.y; rz += p.z; rw += p.w;
        }
        float v = leaky(rx) * dz.x + leaky(ry) * dz.y +
                  leaky(rz) * dz.z + leaky(rw) * dz.w;
        v += __shfl_down_sync(0x0000ffffu, v, 8, 16);
        v += __shfl_down_sync(0x0000ffffu, v, 4, 16);
        v += __shfl_down_sync(0x0000ffffu, v, 2, 16);
        v += __shfl_down_sync(0x0000ffffu, v, 1, 16);
        if (t == 0) out[b] = v;
    }
}

// ---------------------------------------------------------------------------
extern "C" void kernel_launch(void* const* d_in, const int* in_sizes, int n_in,
                              void* d_out, int out_size) {
    const float* E_s = (const float*)d_in[0];
    const float* E_d = (const float*)d_in[1];
    // weights: W_dsd_21, W_dsd_22, W_dsd_11, W_dsd_12, W_usu_3, W_usu_21, W_usu_22, W_usu_1
    k_transpose<<<8, 1024>>>((const float*)d_in[2], (const float*)d_in[3],
                             (const float*)d_in[4], (const float*)d_in[5],
                             (const float*)d_in[6], (const float*)d_in[7],
                             (const float*)d_in[8], (const float*)d_in[9]);

    k_inner<<<NB * 8 + NB, 128>>>(E_s, E_d,
                                  (const int*)d_in[10], (const int*)d_in[11],
                                  (const int*)d_in[12], (const int*)d_in[13],
                                  (const int*)d_in[14], (const int*)d_in[15]);

    k_final<<<NB, 128>>>((const int*)d_in[13], (float*)d_out);
}